// round 5
// baseline (speedup 1.0000x reference)
#include <cuda_runtime.h>

// Problem constants (shapes fixed by the dataset)
#define SRC_SIZE 2000000
#define TABLE_SIZE (2 * SRC_SIZE)

#define NBLOCKS 1184      // 148 SMs * 8 CTAs — single wave, guaranteed resident
#define BLOCK   256
#define NTHREADS (NBLOCKS * BLOCK)

// 16 MB scratch: concatenated gathered layer inputs (phase 1 output).
__device__ float g_layer[TABLE_SIZE];

// Device-wide barrier counter. Monotonically increasing across graph replays
// (epoch = counter / NBLOCKS), so no reset race and fully deterministic.
__device__ unsigned int g_bar = 0;

__global__ void __launch_bounds__(BLOCK, 8)
fused_rule(const float* __restrict__ va,
           const float* __restrict__ vb,
           const int4*  __restrict__ ia4,
           const int4*  __restrict__ ib4,
           const int4*  __restrict__ cidx4,
           const float* __restrict__ w,
           float*       __restrict__ out,
           int quarter,            // src_size / 4
           int num_neurons)
{
    const int gtid = blockIdx.x * BLOCK + threadIdx.x;

    // ---- Phase 1: g_layer = concat(va[ia], vb[ib]), grid-stride ----
    {
        float4* outa = (float4*)g_layer;
        float4* outb = (float4*)(g_layer + 4 * quarter);
        for (int i = gtid; i < quarter; i += NTHREADS) {
            int4 ja = __ldcs(&ia4[i]);
            int4 jb = __ldcs(&ib4[i]);
            float a0 = __ldcg(&va[ja.x]);
            float a1 = __ldcg(&va[ja.y]);
            float a2 = __ldcg(&va[ja.z]);
            float a3 = __ldcg(&va[ja.w]);
            float b0 = __ldcg(&vb[jb.x]);
            float b1 = __ldcg(&vb[jb.y]);
            float b2 = __ldcg(&vb[jb.z]);
            float b3 = __ldcg(&vb[jb.w]);
            outa[i] = make_float4(a0, a1, a2, a3);
            outb[i] = make_float4(b0, b1, b2, b3);
        }
    }

    // ---- Device-wide barrier (all blocks resident: single-wave launch) ----
    __syncthreads();
    if (threadIdx.x == 0) {
        __threadfence();                                  // publish g_layer
        unsigned old = atomicAdd(&g_bar, 1u);
        unsigned target = (old / NBLOCKS + 1u) * NBLOCKS; // end of this epoch
        while (*(volatile unsigned*)&g_bar < target)
            __nanosleep(64);
    }
    __syncthreads();
    __threadfence();                                      // acquire g_layer

    // ---- Phase 2: per neuron — 8 gathers, weighted sum, tanh ----
    for (int t = gtid; t < num_neurons; t += NTHREADS) {
        int4 c0 = __ldcs(&cidx4[2 * t]);
        int4 c1 = __ldcs(&cidx4[2 * t + 1]);

        // 8 independent random gathers (MLP = 8), L2-only
        float v0 = __ldcg(&g_layer[c0.x]);
        float v1 = __ldcg(&g_layer[c0.y]);
        float v2 = __ldcg(&g_layer[c0.z]);
        float v3 = __ldcg(&g_layer[c0.w]);
        float v4 = __ldcg(&g_layer[c1.x]);
        float v5 = __ldcg(&g_layer[c1.y]);
        float v6 = __ldcg(&g_layer[c1.z]);
        float v7 = __ldcg(&g_layer[c1.w]);

        float s = v0 * __ldg(&w[0]);
        s = fmaf(v1, __ldg(&w[1]), s);
        s = fmaf(v2, __ldg(&w[2]), s);
        s = fmaf(v3, __ldg(&w[3]), s);
        s = fmaf(v4, __ldg(&w[4]), s);
        s = fmaf(v5, __ldg(&w[5]), s);
        s = fmaf(v6, __ldg(&w[6]), s);
        s = fmaf(v7, __ldg(&w[7]), s);

        __stcs(&out[t], tanhf(s));
    }
}

extern "C" void kernel_launch(void* const* d_in, const int* in_sizes, int n_in,
                              void* d_out, int out_size)
{
    // metadata order: values_a, values_b, weights, idx_a, idx_b, concat_idx
    const float* va   = (const float*)d_in[0];
    const float* vb   = (const float*)d_in[1];
    const float* w    = (const float*)d_in[2];
    const int*   ia   = (const int*)d_in[3];
    const int*   ib   = (const int*)d_in[4];
    const int*   cidx = (const int*)d_in[5];
    float* out = (float*)d_out;

    int src_size    = in_sizes[0];      // 2,000,000 (divisible by 4)
    int num_neurons = out_size;         // 4,000,000

    fused_rule<<<NBLOCKS, BLOCK>>>(va, vb,
                                   (const int4*)ia, (const int4*)ib,
                                   (const int4*)cidx, w, out,
                                   src_size / 4, num_neurons);
}

// round 6
// speedup vs baseline: 1.0347x; 1.0347x over previous
#include <cuda_runtime.h>

// Problem constants (shapes fixed by the dataset)
#define SRC_SIZE 2000000
#define TABLE_SIZE (2 * SRC_SIZE)

// 16 MB scratch: concatenated gathered layer inputs (stage 1 output).
__device__ float g_layer[TABLE_SIZE];

// Stage 1: g_layer = concat(values_a[idx_a], values_b[idx_b]).
// One thread handles 8 consecutive a-entries and 8 b-entries (16 gathers in flight).
__global__ void __launch_bounds__(256)
stage1_gather(const float* __restrict__ va,
              const float* __restrict__ vb,
              const int4*  __restrict__ ia4,
              const int4*  __restrict__ ib4,
              int eighth)                     // = src_size / 8
{
    int i = blockIdx.x * blockDim.x + threadIdx.x;
    if (i >= eighth) return;

    // 2 int4 of a-indices + 2 int4 of b-indices (coalesced)
    int4 ja0 = __ldg(&ia4[2 * i]);
    int4 ja1 = __ldg(&ia4[2 * i + 1]);
    int4 jb0 = __ldg(&ib4[2 * i]);
    int4 jb1 = __ldg(&ib4[2 * i + 1]);

    // 16 independent random gathers in flight, L2-only
    float a0 = __ldcg(&va[ja0.x]);
    float a1 = __ldcg(&va[ja0.y]);
    float a2 = __ldcg(&va[ja0.z]);
    float a3 = __ldcg(&va[ja0.w]);
    float a4 = __ldcg(&va[ja1.x]);
    float a5 = __ldcg(&va[ja1.y]);
    float a6 = __ldcg(&va[ja1.z]);
    float a7 = __ldcg(&va[ja1.w]);
    float b0 = __ldcg(&vb[jb0.x]);
    float b1 = __ldcg(&vb[jb0.y]);
    float b2 = __ldcg(&vb[jb0.z]);
    float b3 = __ldcg(&vb[jb0.w]);
    float b4 = __ldcg(&vb[jb1.x]);
    float b5 = __ldcg(&vb[jb1.y]);
    float b6 = __ldcg(&vb[jb1.z]);
    float b7 = __ldcg(&vb[jb1.w]);

    float4* outa = (float4*)g_layer;
    float4* outb = (float4*)(g_layer + 8 * eighth);
    outa[2 * i]     = make_float4(a0, a1, a2, a3);
    outa[2 * i + 1] = make_float4(a4, a5, a6, a7);
    outb[2 * i]     = make_float4(b0, b1, b2, b3);
    outb[2 * i + 1] = make_float4(b4, b5, b6, b7);
}

// Stage 2: one thread per neuron — 8 random gathers, weighted sum, tanh.
// Pinned at the L1tex wavefront floor (32M wavefronts chip-wide); unchanged
// from the measured-best R4 formulation.
__global__ void __launch_bounds__(256)
stage2_rule(const int4* __restrict__ cidx4,   // 2 int4s per neuron
            const float* __restrict__ w,      // 8 weights (L1-resident broadcast)
            float* __restrict__ out,
            int num_neurons)
{
    int t = blockIdx.x * blockDim.x + threadIdx.x;
    if (t >= num_neurons) return;

    int4 c0 = __ldcs(&cidx4[2 * t]);
    int4 c1 = __ldcs(&cidx4[2 * t + 1]);

    float w0 = __ldg(&w[0]), w1 = __ldg(&w[1]), w2 = __ldg(&w[2]), w3 = __ldg(&w[3]);
    float w4 = __ldg(&w[4]), w5 = __ldg(&w[5]), w6 = __ldg(&w[6]), w7 = __ldg(&w[7]);

    // 8 independent random gathers (MLP = 8), L2-only
    float v0 = __ldcg(&g_layer[c0.x]);
    float v1 = __ldcg(&g_layer[c0.y]);
    float v2 = __ldcg(&g_layer[c0.z]);
    float v3 = __ldcg(&g_layer[c0.w]);
    float v4 = __ldcg(&g_layer[c1.x]);
    float v5 = __ldcg(&g_layer[c1.y]);
    float v6 = __ldcg(&g_layer[c1.z]);
    float v7 = __ldcg(&g_layer[c1.w]);

    float s = v0 * w0;
    s = fmaf(v1, w1, s);
    s = fmaf(v2, w2, s);
    s = fmaf(v3, w3, s);
    s = fmaf(v4, w4, s);
    s = fmaf(v5, w5, s);
    s = fmaf(v6, w6, s);
    s = fmaf(v7, w7, s);

    __stcs(&out[t], tanhf(s));
}

extern "C" void kernel_launch(void* const* d_in, const int* in_sizes, int n_in,
                              void* d_out, int out_size)
{
    // metadata order: values_a, values_b, weights, idx_a, idx_b, concat_idx
    const float* va   = (const float*)d_in[0];
    const float* vb   = (const float*)d_in[1];
    const float* w    = (const float*)d_in[2];
    const int*   ia   = (const int*)d_in[3];
    const int*   ib   = (const int*)d_in[4];
    const int*   cidx = (const int*)d_in[5];
    float* out = (float*)d_out;

    int src_size    = in_sizes[0];      // 2,000,000 (divisible by 8)
    int num_neurons = out_size;         // 4,000,000

    {
        int eighth = src_size / 8;
        int threads = 256;
        int blocks = (eighth + threads - 1) / threads;
        stage1_gather<<<blocks, threads>>>(va, vb,
                                           (const int4*)ia, (const int4*)ib,
                                           eighth);
    }
    {
        int threads = 256;
        int blocks = (num_neurons + threads - 1) / threads;
        stage2_rule<<<blocks, threads>>>((const int4*)cidx, w, out, num_neurons);
    }
}

// round 7
// speedup vs baseline: 1.0640x; 1.0283x over previous
#include <cuda_runtime.h>

// Problem constants (shapes fixed by the dataset)
#define SRC_SIZE 2000000
#define TABLE_SIZE (2 * SRC_SIZE)

// 16 MB scratch: concatenated gathered layer inputs (stage 1 output).
__device__ float g_layer[TABLE_SIZE];

// Stage 1: g_layer = concat(values_a[idx_a], values_b[idx_b]).
// R4 formulation (measured best): 4 a-gathers + 4 b-gathers per thread.
__global__ void __launch_bounds__(256)
stage1_gather(const float* __restrict__ va,
              const float* __restrict__ vb,
              const int4*  __restrict__ ia4,
              const int4*  __restrict__ ib4,
              int quarter)                    // = src_size / 4
{
    int i = blockIdx.x * blockDim.x + threadIdx.x;
    if (i >= quarter) return;

    int4 ja = __ldcs(&ia4[i]);
    int4 jb = __ldcs(&ib4[i]);

    float a0 = __ldcg(&va[ja.x]);
    float a1 = __ldcg(&va[ja.y]);
    float a2 = __ldcg(&va[ja.z]);
    float a3 = __ldcg(&va[ja.w]);
    float b0 = __ldcg(&vb[jb.x]);
    float b1 = __ldcg(&vb[jb.y]);
    float b2 = __ldcg(&vb[jb.z]);
    float b3 = __ldcg(&vb[jb.w]);

    float4* outa = (float4*)g_layer;
    float4* outb = (float4*)(g_layer + 4 * quarter);
    outa[i] = make_float4(a0, a1, a2, a3);
    outb[i] = make_float4(b0, b1, b2, b3);
}

// Stage 2 with PDL: prefetch indices + weights (independent of stage 1),
// then wait for stage 1's memory to be visible, then gather.
__global__ void __launch_bounds__(256)
stage2_rule(const int4* __restrict__ cidx4,   // 2 int4s per neuron
            const float* __restrict__ w,      // 8 weights
            float* __restrict__ out,
            int num_neurons)
{
    int t = blockIdx.x * blockDim.x + threadIdx.x;

    int4 c0, c1;
    float w0, w1, w2, w3, w4, w5, w6, w7;
    if (t < num_neurons) {
        // Prefetch: none of this depends on g_layer — overlaps stage 1's tail.
        c0 = __ldcs(&cidx4[2 * t]);
        c1 = __ldcs(&cidx4[2 * t + 1]);
        w0 = __ldg(&w[0]); w1 = __ldg(&w[1]); w2 = __ldg(&w[2]); w3 = __ldg(&w[3]);
        w4 = __ldg(&w[4]); w5 = __ldg(&w[5]); w6 = __ldg(&w[6]); w7 = __ldg(&w[7]);
    }

    // Wait for stage 1 (prior grid) to complete and flush.
    cudaGridDependencySynchronize();

    if (t >= num_neurons) return;

    // 8 independent random gathers (MLP = 8), L2-only
    float v0 = __ldcg(&g_layer[c0.x]);
    float v1 = __ldcg(&g_layer[c0.y]);
    float v2 = __ldcg(&g_layer[c0.z]);
    float v3 = __ldcg(&g_layer[c0.w]);
    float v4 = __ldcg(&g_layer[c1.x]);
    float v5 = __ldcg(&g_layer[c1.y]);
    float v6 = __ldcg(&g_layer[c1.z]);
    float v7 = __ldcg(&g_layer[c1.w]);

    float s = v0 * w0;
    s = fmaf(v1, w1, s);
    s = fmaf(v2, w2, s);
    s = fmaf(v3, w3, s);
    s = fmaf(v4, w4, s);
    s = fmaf(v5, w5, s);
    s = fmaf(v6, w6, s);
    s = fmaf(v7, w7, s);

    __stcs(&out[t], tanhf(s));
}

extern "C" void kernel_launch(void* const* d_in, const int* in_sizes, int n_in,
                              void* d_out, int out_size)
{
    // metadata order: values_a, values_b, weights, idx_a, idx_b, concat_idx
    const float* va   = (const float*)d_in[0];
    const float* vb   = (const float*)d_in[1];
    const float* w    = (const float*)d_in[2];
    const int*   ia   = (const int*)d_in[3];
    const int*   ib   = (const int*)d_in[4];
    const int*   cidx = (const int*)d_in[5];
    float* out = (float*)d_out;

    int src_size    = in_sizes[0];      // 2,000,000 (divisible by 4)
    int num_neurons = out_size;         // 4,000,000

    {
        int quarter = src_size / 4;
        int threads = 256;
        int blocks = (quarter + threads - 1) / threads;
        stage1_gather<<<blocks, threads>>>(va, vb,
                                           (const int4*)ia, (const int4*)ib,
                                           quarter);
    }
    {
        int threads = 256;
        int blocks = (num_neurons + threads - 1) / threads;

        // PDL launch: stage2 blocks may start while stage1's tail drains;
        // cudaGridDependencySynchronize() inside guards the g_layer reads.
        cudaLaunchConfig_t cfg = {};
        cfg.gridDim  = dim3((unsigned)blocks, 1, 1);
        cfg.blockDim = dim3((unsigned)threads, 1, 1);
        cfg.dynamicSmemBytes = 0;
        cfg.stream = 0;
        cudaLaunchAttribute attr[1];
        attr[0].id = cudaLaunchAttributeProgrammaticStreamSerialization;
        attr[0].val.programmaticStreamSerializationAllowed = 1;
        cfg.attrs = attr;
        cfg.numAttrs = 1;

        cudaLaunchKernelEx(&cfg, stage2_rule,
                           (const int4*)cidx, w, out, num_neurons);
    }
}